// round 2
// baseline (speedup 1.0000x reference)
#include <cuda_runtime.h>
#include <cuda_bf16.h>
#include <cfloat>

// Problem constants
#define BB 2
#define NN 2048
#define CC 1024
#define HH 16
#define DD 64
#define MM (BB*NN)            // 4096

// Scratch (device globals; no allocation allowed)
__device__ float g_q[BB*HH*NN*DD];     // [B,H,N,d]
__device__ float g_k[BB*HH*NN*DD];
__device__ float g_v[BB*HH*NN*DD];
__device__ float g_att[MM*CC];         // [B,N,C] attention output

// ---------------------------------------------------------------------------
// GEMM: C[m,j] = sum_k A[m,k]*B[j,k]   (both K-contiguous, "NT")
// 128x128x16 tile, 256 threads, 8x8 per thread in split 4+4 pattern.
// MODE 0: scatter into g_q/g_k/g_v (qkv projection)
// MODE 1: A := g_att, add bias, write to out (final projection)
// ---------------------------------------------------------------------------
template<int MODE>
__global__ void __launch_bounds__(256) gemm_nt(const float* __restrict__ Aarg,
                                               const float* __restrict__ Bmat,
                                               const float* __restrict__ bias,
                                               float* __restrict__ Cout,
                                               int K)
{
    const float* A = (MODE == 1) ? (const float*)g_att : Aarg;

    __shared__ float As[16][128];
    __shared__ float Bs[16][128];

    const int m0 = blockIdx.y * 128;
    const int n0 = blockIdx.x * 128;
    const int tid = threadIdx.x;
    const int tx = tid & 15;
    const int ty = tid >> 4;

    const int lr = tid >> 1;          // 0..127 (row within tile)
    const int lh = (tid & 1) * 8;     // k-offset 0 or 8

    float acc[8][8];
#pragma unroll
    for (int i = 0; i < 8; i++)
#pragma unroll
        for (int j = 0; j < 8; j++) acc[i][j] = 0.f;

    for (int k0 = 0; k0 < K; k0 += 16) {
        float4 a0 = *(const float4*)&A[(size_t)(m0 + lr) * K + k0 + lh];
        float4 a1 = *(const float4*)&A[(size_t)(m0 + lr) * K + k0 + lh + 4];
        float4 b0 = *(const float4*)&Bmat[(size_t)(n0 + lr) * K + k0 + lh];
        float4 b1 = *(const float4*)&Bmat[(size_t)(n0 + lr) * K + k0 + lh + 4];
        __syncthreads();
        As[lh+0][lr] = a0.x; As[lh+1][lr] = a0.y; As[lh+2][lr] = a0.z; As[lh+3][lr] = a0.w;
        As[lh+4][lr] = a1.x; As[lh+5][lr] = a1.y; As[lh+6][lr] = a1.z; As[lh+7][lr] = a1.w;
        Bs[lh+0][lr] = b0.x; Bs[lh+1][lr] = b0.y; Bs[lh+2][lr] = b0.z; Bs[lh+3][lr] = b0.w;
        Bs[lh+4][lr] = b1.x; Bs[lh+5][lr] = b1.y; Bs[lh+6][lr] = b1.z; Bs[lh+7][lr] = b1.w;
        __syncthreads();
#pragma unroll
        for (int kk = 0; kk < 16; kk++) {
            float a[8], b[8];
            float4 t;
            t = *(const float4*)&As[kk][ty * 4];       a[0]=t.x; a[1]=t.y; a[2]=t.z; a[3]=t.w;
            t = *(const float4*)&As[kk][64 + ty * 4];  a[4]=t.x; a[5]=t.y; a[6]=t.z; a[7]=t.w;
            t = *(const float4*)&Bs[kk][tx * 4];       b[0]=t.x; b[1]=t.y; b[2]=t.z; b[3]=t.w;
            t = *(const float4*)&Bs[kk][64 + tx * 4];  b[4]=t.x; b[5]=t.y; b[6]=t.z; b[7]=t.w;
#pragma unroll
            for (int i = 0; i < 8; i++)
#pragma unroll
                for (int j = 0; j < 8; j++)
                    acc[i][j] = fmaf(a[i], b[j], acc[i][j]);
        }
    }

    // Epilogue
#pragma unroll
    for (int ig = 0; ig < 2; ig++) {
#pragma unroll
        for (int ri = 0; ri < 4; ri++) {
            const int i = ig * 4 + ri;
            const int m = m0 + ig * 64 + ty * 4 + ri;
#pragma unroll
            for (int jg = 0; jg < 2; jg++) {
                const int j = n0 + jg * 64 + tx * 4;
                float4 r;
                r.x = acc[i][jg*4+0]; r.y = acc[i][jg*4+1];
                r.z = acc[i][jg*4+2]; r.w = acc[i][jg*4+3];
                if (MODE == 0) {
                    const int s  = j >> 10;           // 0:q 1:k 2:v
                    const int h  = (j >> 6) & 15;
                    const int dd = j & 63;
                    const int bidx = m >> 11;
                    const int n    = m & 2047;
                    float* dst = (s == 0) ? g_q : (s == 1) ? g_k : g_v;
                    *(float4*)&dst[(((size_t)(bidx * HH + h) * NN + n) << 6) + dd] = r;
                } else {
                    float4 bi = *(const float4*)&bias[j];
                    r.x += bi.x; r.y += bi.y; r.z += bi.z; r.w += bi.w;
                    *(float4*)&Cout[(size_t)m * CC + j] = r;
                }
            }
        }
    }
}

// ---------------------------------------------------------------------------
// LayerNorm over d=64 per (b,h,n) vector. One warp per vector.
// which==0 -> g_q, which==1 -> g_k
// ---------------------------------------------------------------------------
__global__ void __launch_bounds__(256) ln_kernel(int which,
                                                 const float* __restrict__ gamma,
                                                 const float* __restrict__ beta)
{
    float* buf = which ? g_k : g_q;
    const int vec  = blockIdx.x * 8 + (threadIdx.x >> 5);
    const int lane = threadIdx.x & 31;
    float2 v = *(float2*)&buf[(size_t)vec * 64 + lane * 2];
    float s  = v.x + v.y;
    float sq = v.x * v.x + v.y * v.y;
#pragma unroll
    for (int m = 16; m >= 1; m >>= 1) {
        s  += __shfl_xor_sync(0xffffffffu, s,  m);
        sq += __shfl_xor_sync(0xffffffffu, sq, m);
    }
    const float mean = s * (1.f / 64.f);
    const float var  = sq * (1.f / 64.f) - mean * mean;
    const float rstd = rsqrtf(var + 1e-5f);
    float2 g  = *(const float2*)&gamma[lane * 2];
    float2 be = *(const float2*)&beta[lane * 2];
    v.x = (v.x - mean) * rstd * g.x + be.x;
    v.y = (v.y - mean) * rstd * g.y + be.y;
    *(float2*)&buf[(size_t)vec * 64 + lane * 2] = v;
}

// ---------------------------------------------------------------------------
// Flash-style attention. Block = 64 queries of one (b,h); loop key tiles of 64.
// 256 threads as 16x16; each thread owns a 4x4 micro-tile (rows ty*4.., cols tx*4..).
// SMEM: Qt (transposed 64x64) + KV (K transposed / V normal, shared) + Pt
// (P transposed) = 48KB static.
// ---------------------------------------------------------------------------
__global__ void __launch_bounds__(256) attn_kernel(const unsigned char* __restrict__ mask)
{
    __shared__ float Qt[64 * 64];
    __shared__ float KV[64 * 64];
    __shared__ float Pt[64 * 64];

    const int bh = blockIdx.y;          // 0..31
    const int b  = bh >> 4;
    const int h  = bh & 15;
    const int n0 = blockIdx.x * 64;
    const int tid = threadIdx.x;
    const int tx = tid & 15;
    const int ty = tid >> 4;

    const float* Qg = g_q + ((size_t)bh * NN + n0) * DD;
    const float* Kg = g_k + (size_t)bh * NN * DD;
    const float* Vg = g_v + (size_t)bh * NN * DD;

    const int lr = tid >> 2;   // 0..63 row
    const int lq = tid & 3;    // float4 lane within row

    // Load Q tile, transposed: Qt[i][r] = Q[r][i]
#pragma unroll
    for (int w = 0; w < 4; w++) {
        const int i4 = w * 4 + lq;
        float4 q = *(const float4*)&Qg[(size_t)lr * DD + i4 * 4];
        Qt[(i4*4+0)*64 + lr] = q.x;
        Qt[(i4*4+1)*64 + lr] = q.y;
        Qt[(i4*4+2)*64 + lr] = q.z;
        Qt[(i4*4+3)*64 + lr] = q.w;
    }

    float m_r[4], l_r[4], o[4][4];
#pragma unroll
    for (int ri = 0; ri < 4; ri++) {
        m_r[ri] = -3.4e38f; l_r[ri] = 0.f;
#pragma unroll
        for (int ci = 0; ci < 4; ci++) o[ri][ci] = 0.f;
    }

    const unsigned char* mrow[4];
#pragma unroll
    for (int ri = 0; ri < 4; ri++)
        mrow[ri] = mask + ((size_t)(b * NN + n0 + ty * 4 + ri)) * NN;

    for (int j0 = 0; j0 < NN; j0 += 64) {
        __syncthreads();   // B0: previous PV reads of KV/Pt complete (covers Qt on iter 0)
        // Load K tile transposed: KV[i][j] = K[j0+j][i]
#pragma unroll
        for (int w = 0; w < 4; w++) {
            const int i4 = w * 4 + lq;
            float4 kk = *(const float4*)&Kg[(size_t)(j0 + lr) * DD + i4 * 4];
            KV[(i4*4+0)*64 + lr] = kk.x;
            KV[(i4*4+1)*64 + lr] = kk.y;
            KV[(i4*4+2)*64 + lr] = kk.z;
            KV[(i4*4+3)*64 + lr] = kk.w;
        }
        __syncthreads();   // B1: K tile ready

        // S = Q K^T (4x4 micro-tile per thread)
        float s[4][4];
#pragma unroll
        for (int ri = 0; ri < 4; ri++)
#pragma unroll
            for (int ci = 0; ci < 4; ci++) s[ri][ci] = 0.f;
#pragma unroll 8
        for (int i = 0; i < 64; i++) {
            float4 a = *(const float4*)&Qt[i * 64 + ty * 4];
            float4 bb = *(const float4*)&KV[i * 64 + tx * 4];
            float av[4] = {a.x, a.y, a.z, a.w};
            float bv[4] = {bb.x, bb.y, bb.z, bb.w};
#pragma unroll
            for (int ri = 0; ri < 4; ri++)
#pragma unroll
                for (int ci = 0; ci < 4; ci++)
                    s[ri][ci] = fmaf(av[ri], bv[ci], s[ri][ci]);
        }

        // scale + mask
#pragma unroll
        for (int ri = 0; ri < 4; ri++) {
            uchar4 mv = *(const uchar4*)&mrow[ri][j0 + tx * 4];
            s[ri][0] = mv.x ? -3.4e38f : s[ri][0] * 0.125f;
            s[ri][1] = mv.y ? -3.4e38f : s[ri][1] * 0.125f;
            s[ri][2] = mv.z ? -3.4e38f : s[ri][2] * 0.125f;
            s[ri][3] = mv.w ? -3.4e38f : s[ri][3] * 0.125f;
        }

        // online softmax update
        float p[4][4];
#pragma unroll
        for (int ri = 0; ri < 4; ri++) {
            float rm = fmaxf(fmaxf(s[ri][0], s[ri][1]), fmaxf(s[ri][2], s[ri][3]));
#pragma unroll
            for (int m = 1; m <= 8; m <<= 1)
                rm = fmaxf(rm, __shfl_xor_sync(0xffffffffu, rm, m));
            const float mnew  = fmaxf(m_r[ri], rm);
            const float alpha = __expf(m_r[ri] - mnew);
            m_r[ri] = mnew;
            float lsum = 0.f;
#pragma unroll
            for (int ci = 0; ci < 4; ci++) {
                p[ri][ci] = __expf(s[ri][ci] - mnew);
                lsum += p[ri][ci];
            }
#pragma unroll
            for (int m = 1; m <= 8; m <<= 1)
                lsum += __shfl_xor_sync(0xffffffffu, lsum, m);
            l_r[ri] = l_r[ri] * alpha + lsum;
#pragma unroll
            for (int ci = 0; ci < 4; ci++) o[ri][ci] *= alpha;
        }

        // store P transposed: Pt[j][r] = p
#pragma unroll
        for (int ci = 0; ci < 4; ci++)
#pragma unroll
            for (int ri = 0; ri < 4; ri++)
                Pt[(tx*4+ci)*64 + (ty*4+ri)] = p[ri][ci];

        __syncthreads();   // B2: Pt written, S-stage KV reads done

        // Load V tile (normal layout) into KV
#pragma unroll
        for (int w = 0; w < 4; w++) {
            const int i4 = w * 4 + lq;
            *(float4*)&KV[lr * 64 + i4 * 4] =
                *(const float4*)&Vg[(size_t)(j0 + lr) * DD + i4 * 4];
        }
        __syncthreads();   // B3: V ready

        // O += P V
#pragma unroll 8
        for (int jj = 0; jj < 64; jj++) {
            float4 pv = *(const float4*)&Pt[jj * 64 + ty * 4];
            float4 vv = *(const float4*)&KV[jj * 64 + tx * 4];
            float pa[4] = {pv.x, pv.y, pv.z, pv.w};
            float va[4] = {vv.x, vv.y, vv.z, vv.w};
#pragma unroll
            for (int ri = 0; ri < 4; ri++)
#pragma unroll
                for (int ci = 0; ci < 4; ci++)
                    o[ri][ci] = fmaf(pa[ri], va[ci], o[ri][ci]);
        }
    }

    // write out: att[b, n, h*64 + c]
#pragma unroll
    for (int ri = 0; ri < 4; ri++) {
        const float inv = 1.f / l_r[ri];
        float4 r;
        r.x = o[ri][0] * inv; r.y = o[ri][1] * inv;
        r.z = o[ri][2] * inv; r.w = o[ri][3] * inv;
        const size_t row = (size_t)(b * NN + n0 + ty * 4 + ri);
        *(float4*)&g_att[row * CC + h * DD + tx * 4] = r;
    }
}

// ---------------------------------------------------------------------------
extern "C" void kernel_launch(void* const* d_in, const int* in_sizes, int n_in,
                              void* d_out, int out_size)
{
    const float*         x       = (const float*)d_in[0];
    const unsigned char* mask    = (const unsigned char*)d_in[1];
    const float*         w_qkv   = (const float*)d_in[2];
    const float*         w_proj  = (const float*)d_in[3];
    const float*         b_proj  = (const float*)d_in[4];
    const float*         q_gamma = (const float*)d_in[5];
    const float*         q_beta  = (const float*)d_in[6];
    const float*         k_gamma = (const float*)d_in[7];
    const float*         k_beta  = (const float*)d_in[8];
    float*               out     = (float*)d_out;

    // 1) QKV projection: [4096,1024] x [3072,1024]^T -> scatter q/k/v [B,H,N,d]
    gemm_nt<0><<<dim3(3 * CC / 128, MM / 128), 256>>>(x, w_qkv, nullptr, nullptr, CC);

    // 2) Per-head LayerNorm on q and k
    ln_kernel<<<(BB * HH * NN) / 8, 256>>>(0, q_gamma, q_beta);
    ln_kernel<<<(BB * HH * NN) / 8, 256>>>(1, k_gamma, k_beta);

    // 3) Attention -> g_att [B,N,C]
    attn_kernel<<<dim3(NN / 64, BB * HH), 256>>>(mask);

    // 4) Output projection + bias
    gemm_nt<1><<<dim3(CC / 128, MM / 128), 256>>>(nullptr, w_proj, b_proj, out, CC);
}

// round 4
// speedup vs baseline: 1.1198x; 1.1198x over previous
#include <cuda_runtime.h>
#include <cstdint>
#include <cstddef>

// Problem constants
#define BB 2
#define NN 2048
#define CC 1024
#define HH 16
#define DD 64
#define MM (BB*NN)            // 4096
#define K2 2048               // split (hi|lo) K

// Scratch (device globals; no allocation allowed)
__device__ float g_q[BB*HH*NN*DD];     // [B,H,N,d]
__device__ float g_k[BB*HH*NN*DD];
__device__ float g_v[BB*HH*NN*DD];
__device__ float g_att[MM*CC];         // [B,N,C] attention output
__device__ float g_x2[MM*K2];          // x split to (hi|lo) tf32
__device__ float g_wqkv2[3*CC*K2];
__device__ float g_wp2[CC*K2];
__device__ float g_att2[MM*K2];

// ---------------------------------------------------------------------------
// helpers
// ---------------------------------------------------------------------------
__device__ __forceinline__ uint32_t smem_u32(const void* p) {
    uint32_t a;
    asm("{ .reg .u64 t; cvta.to.shared.u64 t, %1; cvt.u32.u64 %0, t; }" : "=r"(a) : "l"(p));
    return a;
}
__device__ __forceinline__ float tf32_rna(float x) {
    uint32_t u;
    asm("cvt.rna.tf32.f32 %0, %1;" : "=r"(u) : "f"(x));
    return __uint_as_float(u);
}
__device__ __forceinline__ void cp16(uint32_t dst, const void* src) {
    asm volatile("cp.async.cg.shared.global [%0], [%1], 16;" :: "r"(dst), "l"(src));
}
__device__ __forceinline__ void cp_commit() {
    asm volatile("cp.async.commit_group;" ::: "memory");
}
template<int N>
__device__ __forceinline__ void cp_wait() {
    asm volatile("cp.async.wait_group %0;" :: "n"(N) : "memory");
}
__device__ __forceinline__ void ldsm4(uint32_t addr, uint32_t& r0, uint32_t& r1,
                                      uint32_t& r2, uint32_t& r3) {
    asm volatile("ldmatrix.sync.aligned.m8n8.x4.shared.b16 {%0,%1,%2,%3}, [%4];"
                 : "=r"(r0), "=r"(r1), "=r"(r2), "=r"(r3) : "r"(addr));
}
__device__ __forceinline__ void mma_tf32(float* d, const uint32_t* a, const uint32_t* b) {
    asm volatile(
        "mma.sync.aligned.m16n8k8.row.col.f32.tf32.tf32.f32 "
        "{%0,%1,%2,%3}, {%4,%5,%6,%7}, {%8,%9}, {%0,%1,%2,%3};"
        : "+f"(d[0]), "+f"(d[1]), "+f"(d[2]), "+f"(d[3])
        : "r"(a[0]), "r"(a[1]), "r"(a[2]), "r"(a[3]), "r"(b[0]), "r"(b[1]));
}

// ---------------------------------------------------------------------------
// Split fp32 -> (tf32 hi | tf32 lo) concatenated along K (1024 -> 2048/row).
// ---------------------------------------------------------------------------
__global__ void __launch_bounds__(256) split_tf32(const float* __restrict__ src,
                                                  float* __restrict__ dst, int n4)
{
    int i = blockIdx.x * 256 + threadIdx.x;
    if (i >= n4) return;
    int r = i >> 8, c4 = i & 255;
    float4 v = ((const float4*)src)[(size_t)r * 256 + c4];
    float4 hi, lo;
    hi.x = tf32_rna(v.x); lo.x = tf32_rna(v.x - hi.x);
    hi.y = tf32_rna(v.y); lo.y = tf32_rna(v.y - hi.y);
    hi.z = tf32_rna(v.z); lo.z = tf32_rna(v.z - hi.z);
    hi.w = tf32_rna(v.w); lo.w = tf32_rna(v.w - hi.w);
    ((float4*)dst)[(size_t)r * 512 + c4]       = hi;
    ((float4*)dst)[(size_t)r * 512 + 256 + c4] = lo;
}

// ---------------------------------------------------------------------------
// mma.sync tf32 GEMM:  C[m,n] = sum_k A[m,k]*B[n,k], K=2048 (hi|lo split).
// CTA 128x128, 8 warps (2x4), warp tile 64x32, k-step 32 floats, 3-stage
// cp.async pipeline. smem/stage = 32KB (A 16K + B 16K), total 96KB dynamic.
// MODE 0: scatter q/k/v.  MODE 1: +bias -> Cout.
// ---------------------------------------------------------------------------
#define GSTAGE 32768u
#define GSMEM  (3u * GSTAGE)

template<int MODE>
__global__ void __launch_bounds__(256, 1) gemm_mma(const float* __restrict__ A,
                                                   const float* __restrict__ Bm,
                                                   const float* __restrict__ bias,
                                                   float* __restrict__ Cout)
{
    extern __shared__ __align__(128) char smem[];
    const uint32_t sb = smem_u32(smem);
    const int tid  = threadIdx.x;
    const int wid  = tid >> 5;
    const int lane = tid & 31;
    const int wm = wid & 1;        // 2 warps over M (64 each)
    const int wn = wid >> 1;       // 4 warps over N (32 each)
    const int m0 = blockIdx.y * 128;
    const int n0 = blockIdx.x * 128;

    // ---- loader geometry: 256 threads, A/B each 128 rows x 8 chunks of 16B
    const int arow  = tid >> 1;
    const int acol4 = (tid & 1) * 4;          // chunk base 0 or 4
    const float* gA = A  + (size_t)(m0 + arow) * K2 + acol4 * 4;
    const float* gB = Bm + (size_t)(n0 + arow) * K2 + acol4 * 4;
    uint32_t sAo[4], sBo[4];
#pragma unroll
    for (int i = 0; i < 4; i++) {
        const int ch = acol4 + i;
        sAo[i] = (uint32_t)(arow * 128 + ((ch ^ (arow & 7)) * 16));
        sBo[i] = 16384u + (uint32_t)(arow * 128 + ((ch ^ (arow & 7)) * 16));
    }

    // ---- ldmatrix geometry
    // A tiles: lane groups of 8 -> (T0 rows+0 k0-3, T1 rows+8 k0-3, T2 rows+0 k4-7, T3 rows+8 k4-7)
    const int ahi = lane >> 4;                 // chunk add for T2/T3
    uint32_t aRow[4]; int aXor[4];
#pragma unroll
    for (int mt = 0; mt < 4; mt++) {
        const int r = wm * 64 + mt * 16 + ((lane >> 3) & 1) * 8 + (lane & 7);
        aRow[mt] = (uint32_t)(r * 128);
        aXor[mt] = r & 7;
    }
    const int bhi = (lane >> 3) & 1;           // chunk add for T1/T3
    uint32_t bRow[2]; int bXor[2];
#pragma unroll
    for (int ntp = 0; ntp < 2; ntp++) {
        const int r = wn * 32 + ntp * 16 + ((lane >> 4) & 1) * 8 + (lane & 7);
        bRow[ntp] = 16384u + (uint32_t)(r * 128);
        bXor[ntp] = r & 7;
    }

    float acc[4][4][4];
#pragma unroll
    for (int i = 0; i < 4; i++)
#pragma unroll
        for (int j = 0; j < 4; j++)
#pragma unroll
            for (int c = 0; c < 4; c++) acc[i][j][c] = 0.f;

    // ---- prologue: stages 0,1
#pragma unroll
    for (int st = 0; st < 2; st++) {
        const uint32_t base = sb + st * GSTAGE;
        const float* pa = gA + st * 32;
        const float* pb = gB + st * 32;
#pragma unroll
        for (int i = 0; i < 4; i++) { cp16(base + sAo[i], pa + i * 4); cp16(base + sBo[i], pb + i * 4); }
        cp_commit();
    }

    for (int it = 0; it < 64; it++) {
        if (it < 63) cp_wait<1>(); else cp_wait<0>();
        __syncthreads();
        if (it + 2 < 64) {
            const int st = (it + 2) % 3;
            const uint32_t base = sb + st * GSTAGE;
            const float* pa = gA + (it + 2) * 32;
            const float* pb = gB + (it + 2) * 32;
#pragma unroll
            for (int i = 0; i < 4; i++) { cp16(base + sAo[i], pa + i * 4); cp16(base + sBo[i], pb + i * 4); }
            cp_commit();
        }
        const uint32_t base = sb + (it % 3) * GSTAGE;
#pragma unroll
        for (int kc = 0; kc < 4; kc++) {
            uint32_t a[4][4], b[2][4];
#pragma unroll
            for (int mt = 0; mt < 4; mt++)
                ldsm4(base + aRow[mt] + (uint32_t)(((kc * 2 + ahi) ^ aXor[mt]) * 16),
                      a[mt][0], a[mt][1], a[mt][2], a[mt][3]);
#pragma unroll
            for (int ntp = 0; ntp < 2; ntp++)
                ldsm4(base + bRow[ntp] + (uint32_t)(((kc * 2 + bhi) ^ bXor[ntp]) * 16),
                      b[ntp][0], b[ntp][1], b[ntp][2], b[ntp][3]);
#pragma unroll
            for (int mt = 0; mt < 4; mt++)
#pragma unroll
                for (int nt = 0; nt < 4; nt++)
                    mma_tf32(acc[mt][nt], a[mt], &b[nt >> 1][(nt & 1) * 2]);
        }
    }

    // ---- epilogue: direct float2 stores from fragments
#pragma unroll
    for (int mt = 0; mt < 4; mt++) {
#pragma unroll
        for (int nt = 0; nt < 4; nt++) {
            const int j  = n0 + wn * 32 + nt * 8 + (lane & 3) * 2;
            const int r0 = m0 + wm * 64 + mt * 16 + (lane >> 2);
#pragma unroll
            for (int half = 0; half < 2; half++) {
                const int m = r0 + half * 8;
                float2 v;
                v.x = acc[mt][nt][half * 2 + 0];
                v.y = acc[mt][nt][half * 2 + 1];
                if (MODE == 0) {
                    const int ssel = j >> 10;
                    const int h    = (j >> 6) & 15;
                    const int dd   = j & 63;
                    const int bi   = m >> 11;
                    const int n    = m & 2047;
                    float* dst = (ssel == 0) ? g_q : (ssel == 1) ? g_k : g_v;
                    *(float2*)&dst[(((size_t)(bi * HH + h) * NN + n) << 6) + dd] = v;
                } else {
                    float2 bv = *(const float2*)&bias[j];
                    v.x += bv.x; v.y += bv.y;
                    *(float2*)&Cout[(size_t)m * CC + j] = v;
                }
            }
        }
    }
}

// ---------------------------------------------------------------------------
// LayerNorm over d=64 per (b,h,n) vector. One warp per vector.
// ---------------------------------------------------------------------------
__global__ void __launch_bounds__(256) ln_kernel(int which,
                                                 const float* __restrict__ gamma,
                                                 const float* __restrict__ beta)
{
    float* buf = which ? g_k : g_q;
    const int vec  = blockIdx.x * 8 + (threadIdx.x >> 5);
    const int lane = threadIdx.x & 31;
    float2 v = *(float2*)&buf[(size_t)vec * 64 + lane * 2];
    float s  = v.x + v.y;
    float sq = v.x * v.x + v.y * v.y;
#pragma unroll
    for (int m = 16; m >= 1; m >>= 1) {
        s  += __shfl_xor_sync(0xffffffffu, s,  m);
        sq += __shfl_xor_sync(0xffffffffu, sq, m);
    }
    const float mean = s * (1.f / 64.f);
    const float var  = sq * (1.f / 64.f) - mean * mean;
    const float rstd = rsqrtf(var + 1e-5f);
    float2 g  = *(const float2*)&gamma[lane * 2];
    float2 be = *(const float2*)&beta[lane * 2];
    v.x = (v.x - mean) * rstd * g.x + be.x;
    v.y = (v.y - mean) * rstd * g.y + be.y;
    *(float2*)&buf[(size_t)vec * 64 + lane * 2] = v;
}

// ---------------------------------------------------------------------------
// Flash-style SIMT attention (unchanged from R2 baseline).
// ---------------------------------------------------------------------------
__global__ void __launch_bounds__(256) attn_kernel(const unsigned char* __restrict__ mask)
{
    __shared__ float Qt[64 * 64];
    __shared__ float KV[64 * 64];
    __shared__ float Pt[64 * 64];

    const int bh = blockIdx.y;
    const int b  = bh >> 4;
    const int h  = bh & 15;
    const int n0 = blockIdx.x * 64;
    const int tid = threadIdx.x;
    const int tx = tid & 15;
    const int ty = tid >> 4;

    const float* Qg = g_q + ((size_t)bh * NN + n0) * DD;
    const float* Kg = g_k + (size_t)bh * NN * DD;
    const float* Vg = g_v + (size_t)bh * NN * DD;

    const int lr = tid >> 2;
    const int lq = tid & 3;

#pragma unroll
    for (int w = 0; w < 4; w++) {
        const int i4 = w * 4 + lq;
        float4 q = *(const float4*)&Qg[(size_t)lr * DD + i4 * 4];
        Qt[(i4*4+0)*64 + lr] = q.x;
        Qt[(i4*4+1)*64 + lr] = q.y;
        Qt[(i4*4+2)*64 + lr] = q.z;
        Qt[(i4*4+3)*64 + lr] = q.w;
    }

    float m_r[4], l_r[4], o[4][4];
#pragma unroll
    for (int ri = 0; ri < 4; ri++) {
        m_r[ri] = -3.4e38f; l_r[ri] = 0.f;
#pragma unroll
        for (int ci = 0; ci < 4; ci++) o[ri][ci] = 0.f;
    }

    const unsigned char* mrow[4];
#pragma unroll
    for (int ri = 0; ri < 4; ri++)
        mrow[ri] = mask + ((size_t)(b * NN + n0 + ty * 4 + ri)) * NN;

    for (int j0 = 0; j0 < NN; j0 += 64) {
        __syncthreads();
#pragma unroll
        for (int w = 0; w < 4; w++) {
            const int i4 = w * 4 + lq;
            float4 kk = *(const float4*)&Kg[(size_t)(j0 + lr) * DD + i4 * 4];
            KV[(i4*4+0)*64 + lr] = kk.x;
            KV[(i4*4+1)*64 + lr] = kk.y;
            KV[(i4*4+2)*64 + lr] = kk.z;
            KV[(i4*4+3)*64 + lr] = kk.w;
        }
        __syncthreads();

        float s[4][4];
#pragma unroll
        for (int ri = 0; ri < 4; ri++)
#pragma unroll
            for (int ci = 0; ci < 4; ci++) s[ri][ci] = 0.f;
#pragma unroll 8
        for (int i = 0; i < 64; i++) {
            float4 a  = *(const float4*)&Qt[i * 64 + ty * 4];
            float4 bb = *(const float4*)&KV[i * 64 + tx * 4];
            float av[4] = {a.x, a.y, a.z, a.w};
            float bv[4] = {bb.x, bb.y, bb.z, bb.w};
#pragma unroll
            for (int ri = 0; ri < 4; ri++)
#pragma unroll
                for (int ci = 0; ci < 4; ci++)
                    s[ri][ci] = fmaf(av[ri], bv[ci], s[ri][ci]);
        }

#pragma unroll
        for (int ri = 0; ri < 4; ri++) {
            uchar4 mv = *(const uchar4*)&mrow[ri][j0 + tx * 4];
            s[ri][0] = mv.x ? -3.4e38f : s[ri][0] * 0.125f;
            s[ri][1] = mv.y ? -3.4e38f : s[ri][1] * 0.125f;
            s[ri][2] = mv.z ? -3.4e38f : s[ri][2] * 0.125f;
            s[ri][3] = mv.w ? -3.4e38f : s[ri][3] * 0.125f;
        }

        float p[4][4];
#pragma unroll
        for (int ri = 0; ri < 4; ri++) {
            float rm = fmaxf(fmaxf(s[ri][0], s[ri][1]), fmaxf(s[ri][2], s[ri][3]));
#pragma unroll
            for (int m = 1; m <= 8; m <<= 1)
                rm = fmaxf(rm, __shfl_xor_sync(0xffffffffu, rm, m));
            const float mnew  = fmaxf(m_r[ri], rm);
            const float alpha = __expf(m_r[ri] - mnew);
            m_r[ri] = mnew;
            float lsum = 0.f;
#pragma unroll
            for (int ci = 0; ci < 4; ci++) {
                p[ri][ci] = __expf(s[ri][ci] - mnew);
                lsum += p[ri][ci];
            }
#pragma unroll
            for (int m = 1; m <= 8; m <<= 1)
                lsum += __shfl_xor_sync(0xffffffffu, lsum, m);
            l_r[ri] = l_r[ri] * alpha + lsum;
#pragma unroll
            for (int ci = 0; ci < 4; ci++) o[ri][ci] *= alpha;
        }

#pragma unroll
        for (int ci = 0; ci < 4; ci++)
#pragma unroll
            for (int ri = 0; ri < 4; ri++)
                Pt[(tx*4+ci)*64 + (ty*4+ri)] = p[ri][ci];

        __syncthreads();

#pragma unroll
        for (int w = 0; w < 4; w++) {
            const int i4 = w * 4 + lq;
            *(float4*)&KV[lr * 64 + i4 * 4] =
                *(const float4*)&Vg[(size_t)(j0 + lr) * DD + i4 * 4];
        }
        __syncthreads();

#pragma unroll 8
        for (int jj = 0; jj < 64; jj++) {
            float4 pv = *(const float4*)&Pt[jj * 64 + ty * 4];
            float4 vv = *(const float4*)&KV[jj * 64 + tx * 4];
            float pa[4] = {pv.x, pv.y, pv.z, pv.w};
            float va[4] = {vv.x, vv.y, vv.z, vv.w};
#pragma unroll
            for (int ri = 0; ri < 4; ri++)
#pragma unroll
                for (int ci = 0; ci < 4; ci++)
                    o[ri][ci] = fmaf(pa[ri], va[ci], o[ri][ci]);
        }
    }

#pragma unroll
    for (int ri = 0; ri < 4; ri++) {
        const float inv = 1.f / l_r[ri];
        float4 r;
        r.x = o[ri][0] * inv; r.y = o[ri][1] * inv;
        r.z = o[ri][2] * inv; r.w = o[ri][3] * inv;
        const size_t row = (size_t)(b * NN + n0 + ty * 4 + ri);
        *(float4*)&g_att[row * CC + h * DD + tx * 4] = r;
    }
}

// ---------------------------------------------------------------------------
extern "C" void kernel_launch(void* const* d_in, const int* in_sizes, int n_in,
                              void* d_out, int out_size)
{
    const float*         x       = (const float*)d_in[0];
    const unsigned char* mask    = (const unsigned char*)d_in[1];
    const float*         w_qkv   = (const float*)d_in[2];
    const float*         w_proj  = (const float*)d_in[3];
    const float*         b_proj  = (const float*)d_in[4];
    const float*         q_gamma = (const float*)d_in[5];
    const float*         q_beta  = (const float*)d_in[6];
    const float*         k_gamma = (const float*)d_in[7];
    const float*         k_beta  = (const float*)d_in[8];
    float*               out     = (float*)d_out;

    float *x2, *wq2, *wp2, *att2, *attp;
    cudaGetSymbolAddress((void**)&x2,   g_x2);
    cudaGetSymbolAddress((void**)&wq2,  g_wqkv2);
    cudaGetSymbolAddress((void**)&wp2,  g_wp2);
    cudaGetSymbolAddress((void**)&att2, g_att2);
    cudaGetSymbolAddress((void**)&attp, g_att);

    cudaFuncSetAttribute(gemm_mma<0>, cudaFuncAttributeMaxDynamicSharedMemorySize, GSMEM);
    cudaFuncSetAttribute(gemm_mma<1>, cudaFuncAttributeMaxDynamicSharedMemorySize, GSMEM);

    // 0) tf32 hi/lo splits of x and weights
    split_tf32<<<MM, 256>>>(x, x2, MM * 256);
    split_tf32<<<3 * CC, 256>>>(w_qkv, wq2, 3 * CC * 256);
    split_tf32<<<CC, 256>>>(w_proj, wp2, CC * 256);

    // 1) QKV projection (tensor cores) -> scatter q/k/v
    gemm_mma<0><<<dim3(3 * CC / 128, MM / 128), 256, GSMEM>>>(x2, wq2, nullptr, nullptr);

    // 2) Per-head LayerNorm on q and k
    ln_kernel<<<(BB * HH * NN) / 8, 256>>>(0, q_gamma, q_beta);
    ln_kernel<<<(BB * HH * NN) / 8, 256>>>(1, k_gamma, k_beta);

    // 3) Attention -> g_att [B,N,C]
    attn_kernel<<<dim3(NN / 64, BB * HH), 256>>>(mask);

    // 4) Split attention output, project (tensor cores) + bias
    split_tf32<<<MM, 256>>>(attp, att2, MM * 256);
    gemm_mma<1><<<dim3(CC / 128, MM / 128), 256, GSMEM>>>(att2, wp2, b_proj, out);
}

// round 5
// speedup vs baseline: 1.2319x; 1.1001x over previous
#include <cuda_runtime.h>
#include <cuda_bf16.h>
#include <cstdint>
#include <cstddef>

// Problem constants
#define BB 2
#define NN 2048
#define CC 1024
#define HH 16
#define DD 64
#define MM (BB*NN)            // 4096
#define K3 3072               // 3-term split K: [hi|hi|lo] x [hi|lo|hi]

// Scratch (device globals; no allocation allowed)
__device__ float g_q[BB*HH*NN*DD];     // [B,H,N,d]
__device__ float g_k[BB*HH*NN*DD];
__device__ float g_v[BB*HH*NN*DD];
__device__ float g_att[MM*CC];         // [B,N,C] attention output
__device__ __nv_bfloat16 g_x2[MM*K3];
__device__ __nv_bfloat16 g_wqkv2[3*CC*K3];
__device__ __nv_bfloat16 g_wp2[CC*K3];
__device__ __nv_bfloat16 g_att2[MM*K3];

// ---------------------------------------------------------------------------
// helpers
// ---------------------------------------------------------------------------
__device__ __forceinline__ uint32_t smem_u32(const void* p) {
    uint32_t a;
    asm("{ .reg .u64 t; cvta.to.shared.u64 t, %1; cvt.u32.u64 %0, t; }" : "=r"(a) : "l"(p));
    return a;
}
__device__ __forceinline__ void cp16(uint32_t dst, const void* src) {
    asm volatile("cp.async.cg.shared.global [%0], [%1], 16;" :: "r"(dst), "l"(src));
}
__device__ __forceinline__ void cp_commit() {
    asm volatile("cp.async.commit_group;" ::: "memory");
}
template<int N>
__device__ __forceinline__ void cp_wait() {
    asm volatile("cp.async.wait_group %0;" :: "n"(N) : "memory");
}
__device__ __forceinline__ void ldsm4(uint32_t addr, uint32_t& r0, uint32_t& r1,
                                      uint32_t& r2, uint32_t& r3) {
    asm volatile("ldmatrix.sync.aligned.m8n8.x4.shared.b16 {%0,%1,%2,%3}, [%4];"
                 : "=r"(r0), "=r"(r1), "=r"(r2), "=r"(r3) : "r"(addr));
}
__device__ __forceinline__ void mma_bf16(float* d, const uint32_t* a,
                                         uint32_t b0, uint32_t b1) {
    asm volatile(
        "mma.sync.aligned.m16n8k16.row.col.f32.bf16.bf16.f32 "
        "{%0,%1,%2,%3}, {%4,%5,%6,%7}, {%8,%9}, {%0,%1,%2,%3};"
        : "+f"(d[0]), "+f"(d[1]), "+f"(d[2]), "+f"(d[3])
        : "r"(a[0]), "r"(a[1]), "r"(a[2]), "r"(a[3]), "r"(b0), "r"(b1));
}

// ---------------------------------------------------------------------------
// Split fp32 row (1024) -> bf16 row (3072).
// IS_B=0 (A operand): [hi | hi | lo].  IS_B=1 (B operand): [hi | lo | hi].
// ---------------------------------------------------------------------------
template<int IS_B>
__global__ void __launch_bounds__(256) split_bf16(const float* __restrict__ src,
                                                  __nv_bfloat16* __restrict__ dst, int n4)
{
    int i = blockIdx.x * 256 + threadIdx.x;
    if (i >= n4) return;
    int r = i >> 8, c4 = i & 255;
    float4 v = ((const float4*)src)[(size_t)r * 256 + c4];
    __nv_bfloat16 h[4], l[4];
    float f[4] = {v.x, v.y, v.z, v.w};
#pragma unroll
    for (int t = 0; t < 4; t++) {
        h[t] = __float2bfloat16_rn(f[t]);
        l[t] = __float2bfloat16_rn(f[t] - __bfloat162float(h[t]));
    }
    uint2 hv, lv;
    hv.x = ((uint32_t)__bfloat16_as_ushort(h[1]) << 16) | __bfloat16_as_ushort(h[0]);
    hv.y = ((uint32_t)__bfloat16_as_ushort(h[3]) << 16) | __bfloat16_as_ushort(h[2]);
    lv.x = ((uint32_t)__bfloat16_as_ushort(l[1]) << 16) | __bfloat16_as_ushort(l[0]);
    lv.y = ((uint32_t)__bfloat16_as_ushort(l[3]) << 16) | __bfloat16_as_ushort(l[2]);
    uint2* base = (uint2*)(dst + (size_t)r * K3);
    base[c4]                 = hv;                    // seg0: hi
    base[256 + c4]           = IS_B ? lv : hv;        // seg1
    base[512 + c4]           = IS_B ? hv : lv;        // seg2
}

// ---------------------------------------------------------------------------
// bf16 mma.sync GEMM:  C[m,n] = sum_k A2[m,k]*B2[n,k], K=3072 (3-term split).
// CTA 128x128, 8 warps (2x4), warp tile 64x32, k-step 64 bf16, 3-stage
// cp.async pipeline. Stage = 32KB (A 16K + B 16K); 96KB dynamic; 2 CTA/SM.
// MODE 0: scatter q/k/v.  MODE 1: +bias -> Cout.
// ---------------------------------------------------------------------------
#define GSTAGE 32768u
#define GSMEM  (3u * GSTAGE)

template<int MODE>
__global__ void __launch_bounds__(256, 2) gemm_mma(const __nv_bfloat16* __restrict__ A,
                                                   const __nv_bfloat16* __restrict__ Bm,
                                                   const float* __restrict__ bias,
                                                   float* __restrict__ Cout)
{
    extern __shared__ __align__(128) char smem[];
    const uint32_t sb = smem_u32(smem);
    const int tid  = threadIdx.x;
    const int wid  = tid >> 5;
    const int lane = tid & 31;
    const int wm = wid & 1;        // 2 warps over M (64 each)
    const int wn = wid >> 1;       // 4 warps over N (32 each)
    const int m0 = blockIdx.y * 128;
    const int n0 = blockIdx.x * 128;

    // ---- loader: 256 threads; A/B 128 rows x 8 chunks of 16B (row = 128B)
    const int arow = tid >> 1;
    const int acb  = (tid & 1) * 4;           // chunk base 0 or 4
    const __nv_bfloat16* gA = A  + (size_t)(m0 + arow) * K3 + acb * 8;
    const __nv_bfloat16* gB = Bm + (size_t)(n0 + arow) * K3 + acb * 8;
    uint32_t sAo[4], sBo[4];
#pragma unroll
    for (int i = 0; i < 4; i++) {
        const int ch = acb + i;
        sAo[i] = (uint32_t)(arow * 128 + ((ch ^ (arow & 7)) * 16));
        sBo[i] = 16384u + sAo[i];
    }

    // ---- ldmatrix geometry
    // tiles per k16: (r+0,c+0)(r+8,c+0)(r+0,c+1)(r+8,c+1); lane->tile = lane>>3
    const int chAdd = lane >> 4;               // chunk add (tiles 2,3)
    uint32_t aRow[4]; int aXor[4];
#pragma unroll
    for (int mt = 0; mt < 4; mt++) {
        const int r = wm * 64 + mt * 16 + ((lane >> 3) & 1) * 8 + (lane & 7);
        aRow[mt] = (uint32_t)(r * 128);
        aXor[mt] = r & 7;
    }
    uint32_t bRow[2]; int bXor[2];
#pragma unroll
    for (int ntp = 0; ntp < 2; ntp++) {
        const int r = wn * 32 + ntp * 16 + ((lane >> 3) & 1) * 8 + (lane & 7);
        bRow[ntp] = 16384u + (uint32_t)(r * 128);
        bXor[ntp] = r & 7;
    }

    float acc[4][4][4];
#pragma unroll
    for (int i = 0; i < 4; i++)
#pragma unroll
        for (int j = 0; j < 4; j++)
#pragma unroll
            for (int c = 0; c < 4; c++) acc[i][j][c] = 0.f;

    // ---- prologue: stages 0,1
#pragma unroll
    for (int st = 0; st < 2; st++) {
        const uint32_t base = sb + st * GSTAGE;
        const __nv_bfloat16* pa = gA + st * 64;
        const __nv_bfloat16* pb = gB + st * 64;
#pragma unroll
        for (int i = 0; i < 4; i++) { cp16(base + sAo[i], pa + i * 8); cp16(base + sBo[i], pb + i * 8); }
        cp_commit();
    }

    const int ITERS = K3 / 64;                 // 48
    for (int it = 0; it < ITERS; it++) {
        if (it < ITERS - 1) cp_wait<1>(); else cp_wait<0>();
        __syncthreads();
        if (it + 2 < ITERS) {
            const uint32_t base = sb + ((it + 2) % 3) * GSTAGE;
            const __nv_bfloat16* pa = gA + (it + 2) * 64;
            const __nv_bfloat16* pb = gB + (it + 2) * 64;
#pragma unroll
            for (int i = 0; i < 4; i++) { cp16(base + sAo[i], pa + i * 8); cp16(base + sBo[i], pb + i * 8); }
            cp_commit();
        }
        const uint32_t base = sb + (it % 3) * GSTAGE;
#pragma unroll
        for (int kc = 0; kc < 4; kc++) {       // 4 x k16 per 64-elem step
            uint32_t a[4][4], b[2][4];
#pragma unroll
            for (int mt = 0; mt < 4; mt++)
                ldsm4(base + aRow[mt] + (uint32_t)(((kc * 2 + chAdd) ^ aXor[mt]) * 16),
                      a[mt][0], a[mt][1], a[mt][2], a[mt][3]);
#pragma unroll
            for (int ntp = 0; ntp < 2; ntp++)
                ldsm4(base + bRow[ntp] + (uint32_t)(((kc * 2 + chAdd) ^ bXor[ntp]) * 16),
                      b[ntp][0], b[ntp][1], b[ntp][2], b[ntp][3]);
#pragma unroll
            for (int mt = 0; mt < 4; mt++)
#pragma unroll
                for (int nt = 0; nt < 4; nt++)
                    mma_bf16(acc[mt][nt], a[mt],
                             b[nt >> 1][nt & 1], b[nt >> 1][(nt & 1) + 2]);
        }
        __syncthreads();
    }

    // ---- epilogue: direct float2 stores from fragments
#pragma unroll
    for (int mt = 0; mt < 4; mt++) {
#pragma unroll
        for (int nt = 0; nt < 4; nt++) {
            const int j  = n0 + wn * 32 + nt * 8 + (lane & 3) * 2;
            const int r0 = m0 + wm * 64 + mt * 16 + (lane >> 2);
#pragma unroll
            for (int half = 0; half < 2; half++) {
                const int m = r0 + half * 8;
                float2 v;
                v.x = acc[mt][nt][half * 2 + 0];
                v.y = acc[mt][nt][half * 2 + 1];
                if (MODE == 0) {
                    const int ssel = j >> 10;
                    const int h    = (j >> 6) & 15;
                    const int dd   = j & 63;
                    const int bi   = m >> 11;
                    const int n    = m & 2047;
                    float* dst = (ssel == 0) ? g_q : (ssel == 1) ? g_k : g_v;
                    *(float2*)&dst[(((size_t)(bi * HH + h) * NN + n) << 6) + dd] = v;
                } else {
                    float2 bv = *(const float2*)&bias[j];
                    v.x += bv.x; v.y += bv.y;
                    *(float2*)&Cout[(size_t)m * CC + j] = v;
                }
            }
        }
    }
}

// ---------------------------------------------------------------------------
// LayerNorm over d=64 per (b,h,n) vector. One warp per vector.
// ---------------------------------------------------------------------------
__global__ void __launch_bounds__(256) ln_kernel(int which,
                                                 const float* __restrict__ gamma,
                                                 const float* __restrict__ beta)
{
    float* buf = which ? g_k : g_q;
    const int vec  = blockIdx.x * 8 + (threadIdx.x >> 5);
    const int lane = threadIdx.x & 31;
    float2 v = *(float2*)&buf[(size_t)vec * 64 + lane * 2];
    float s  = v.x + v.y;
    float sq = v.x * v.x + v.y * v.y;
#pragma unroll
    for (int m = 16; m >= 1; m >>= 1) {
        s  += __shfl_xor_sync(0xffffffffu, s,  m);
        sq += __shfl_xor_sync(0xffffffffu, sq, m);
    }
    const float mean = s * (1.f / 64.f);
    const float var  = sq * (1.f / 64.f) - mean * mean;
    const float rstd = rsqrtf(var + 1e-5f);
    float2 g  = *(const float2*)&gamma[lane * 2];
    float2 be = *(const float2*)&beta[lane * 2];
    v.x = (v.x - mean) * rstd * g.x + be.x;
    v.y = (v.y - mean) * rstd * g.y + be.y;
    *(float2*)&buf[(size_t)vec * 64 + lane * 2] = v;
}

// ---------------------------------------------------------------------------
// Flash-style SIMT attention (unchanged from R2 baseline).
// ---------------------------------------------------------------------------
__global__ void __launch_bounds__(256) attn_kernel(const unsigned char* __restrict__ mask)
{
    __shared__ float Qt[64 * 64];
    __shared__ float KV[64 * 64];
    __shared__ float Pt[64 * 64];

    const int bh = blockIdx.y;
    const int b  = bh >> 4;
    const int h  = bh & 15;
    const int n0 = blockIdx.x * 64;
    const int tid = threadIdx.x;
    const int tx = tid & 15;
    const int ty = tid >> 4;

    const float* Qg = g_q + ((size_t)bh * NN + n0) * DD;
    const float* Kg = g_k + (size_t)bh * NN * DD;
    const float* Vg = g_v + (size_t)bh * NN * DD;

    const int lr = tid >> 2;
    const int lq = tid & 3;

#pragma unroll
    for (int w = 0; w < 4; w++) {
        const int i4 = w * 4 + lq;
        float4 q = *(const float4*)&Qg[(size_t)lr * DD + i4 * 4];
        Qt[(i4*4+0)*64 + lr] = q.x;
        Qt[(i4*4+1)*64 + lr] = q.y;
        Qt[(i4*4+2)*64 + lr] = q.z;
        Qt[(i4*4+3)*64 + lr] = q.w;
    }

    float m_r[4], l_r[4], o[4][4];
#pragma unroll
    for (int ri = 0; ri < 4; ri++) {
        m_r[ri] = -3.4e38f; l_r[ri] = 0.f;
#pragma unroll
        for (int ci = 0; ci < 4; ci++) o[ri][ci] = 0.f;
    }

    const unsigned char* mrow[4];
#pragma unroll
    for (int ri = 0; ri < 4; ri++)
        mrow[ri] = mask + ((size_t)(b * NN + n0 + ty * 4 + ri)) * NN;

    for (int j0 = 0; j0 < NN; j0 += 64) {
        __syncthreads();
#pragma unroll
        for (int w = 0; w < 4; w++) {
            const int i4 = w * 4 + lq;
            float4 kk = *(const float4*)&Kg[(size_t)(j0 + lr) * DD + i4 * 4];
            KV[(i4*4+0)*64 + lr] = kk.x;
            KV[(i4*4+1)*64 + lr] = kk.y;
            KV[(i4*4+2)*64 + lr] = kk.z;
            KV[(i4*4+3)*64 + lr] = kk.w;
        }
        __syncthreads();

        float s[4][4];
#pragma unroll
        for (int ri = 0; ri < 4; ri++)
#pragma unroll
            for (int ci = 0; ci < 4; ci++) s[ri][ci] = 0.f;
#pragma unroll 8
        for (int i = 0; i < 64; i++) {
            float4 a  = *(const float4*)&Qt[i * 64 + ty * 4];
            float4 bb = *(const float4*)&KV[i * 64 + tx * 4];
            float av[4] = {a.x, a.y, a.z, a.w};
            float bv[4] = {bb.x, bb.y, bb.z, bb.w};
#pragma unroll
            for (int ri = 0; ri < 4; ri++)
#pragma unroll
                for (int ci = 0; ci < 4; ci++)
                    s[ri][ci] = fmaf(av[ri], bv[ci], s[ri][ci]);
        }

#pragma unroll
        for (int ri = 0; ri < 4; ri++) {
            uchar4 mv = *(const uchar4*)&mrow[ri][j0 + tx * 4];
            s[ri][0] = mv.x ? -3.4e38f : s[ri][0] * 0.125f;
            s[ri][1] = mv.y ? -3.4e38f : s[ri][1] * 0.125f;
            s[ri][2] = mv.z ? -3.4e38f : s[ri][2] * 0.125f;
            s[ri][3] = mv.w ? -3.4e38f : s[ri][3] * 0.125f;
        }

        float p[4][4];
#pragma unroll
        for (int ri = 0; ri < 4; ri++) {
            float rm = fmaxf(fmaxf(s[ri][0], s[ri][1]), fmaxf(s[ri][2], s[ri][3]));
#pragma unroll
            for (int m = 1; m <= 8; m <<= 1)
                rm = fmaxf(rm, __shfl_xor_sync(0xffffffffu, rm, m));
            const float mnew  = fmaxf(m_r[ri], rm);
            const float alpha = __expf(m_r[ri] - mnew);
            m_r[ri] = mnew;
            float lsum = 0.f;
#pragma unroll
            for (int ci = 0; ci < 4; ci++) {
                p[ri][ci] = __expf(s[ri][ci] - mnew);
                lsum += p[ri][ci];
            }
#pragma unroll
            for (int m = 1; m <= 8; m <<= 1)
                lsum += __shfl_xor_sync(0xffffffffu, lsum, m);
            l_r[ri] = l_r[ri] * alpha + lsum;
#pragma unroll
            for (int ci = 0; ci < 4; ci++) o[ri][ci] *= alpha;
        }

#pragma unroll
        for (int ci = 0; ci < 4; ci++)
#pragma unroll
            for (int ri = 0; ri < 4; ri++)
                Pt[(tx*4+ci)*64 + (ty*4+ri)] = p[ri][ci];

        __syncthreads();

#pragma unroll
        for (int w = 0; w < 4; w++) {
            const int i4 = w * 4 + lq;
            *(float4*)&KV[lr * 64 + i4 * 4] =
                *(const float4*)&Vg[(size_t)(j0 + lr) * DD + i4 * 4];
        }
        __syncthreads();

#pragma unroll 8
        for (int jj = 0; jj < 64; jj++) {
            float4 pv = *(const float4*)&Pt[jj * 64 + ty * 4];
            float4 vv = *(const float4*)&KV[jj * 64 + tx * 4];
            float pa[4] = {pv.x, pv.y, pv.z, pv.w};
            float va[4] = {vv.x, vv.y, vv.z, vv.w};
#pragma unroll
            for (int ri = 0; ri < 4; ri++)
#pragma unroll
                for (int ci = 0; ci < 4; ci++)
                    o[ri][ci] = fmaf(pa[ri], va[ci], o[ri][ci]);
        }
    }

#pragma unroll
    for (int ri = 0; ri < 4; ri++) {
        const float inv = 1.f / l_r[ri];
        float4 r;
        r.x = o[ri][0] * inv; r.y = o[ri][1] * inv;
        r.z = o[ri][2] * inv; r.w = o[ri][3] * inv;
        const size_t row = (size_t)(b * NN + n0 + ty * 4 + ri);
        *(float4*)&g_att[row * CC + h * DD + tx * 4] = r;
    }
}

// ---------------------------------------------------------------------------
extern "C" void kernel_launch(void* const* d_in, const int* in_sizes, int n_in,
                              void* d_out, int out_size)
{
    const float*         x       = (const float*)d_in[0];
    const unsigned char* mask    = (const unsigned char*)d_in[1];
    const float*         w_qkv   = (const float*)d_in[2];
    const float*         w_proj  = (const float*)d_in[3];
    const float*         b_proj  = (const float*)d_in[4];
    const float*         q_gamma = (const float*)d_in[5];
    const float*         q_beta  = (const float*)d_in[6];
    const float*         k_gamma = (const float*)d_in[7];
    const float*         k_beta  = (const float*)d_in[8];
    float*               out     = (float*)d_out;

    __nv_bfloat16 *x2, *wq2, *wp2, *att2;
    float *attp;
    cudaGetSymbolAddress((void**)&x2,   g_x2);
    cudaGetSymbolAddress((void**)&wq2,  g_wqkv2);
    cudaGetSymbolAddress((void**)&wp2,  g_wp2);
    cudaGetSymbolAddress((void**)&att2, g_att2);
    cudaGetSymbolAddress((void**)&attp, g_att);

    cudaFuncSetAttribute(gemm_mma<0>, cudaFuncAttributeMaxDynamicSharedMemorySize, GSMEM);
    cudaFuncSetAttribute(gemm_mma<1>, cudaFuncAttributeMaxDynamicSharedMemorySize, GSMEM);

    // 0) bf16 3-term splits: A-operands [hi|hi|lo], B-operands [hi|lo|hi]
    split_bf16<0><<<MM, 256>>>(x, x2, MM * 256);
    split_bf16<1><<<3 * CC, 256>>>(w_qkv, wq2, 3 * CC * 256);
    split_bf16<1><<<CC, 256>>>(w_proj, wp2, CC * 256);

    // 1) QKV projection (tensor cores) -> scatter q/k/v
    gemm_mma<0><<<dim3(3 * CC / 128, MM / 128), 256, GSMEM>>>(x2, wq2, nullptr, nullptr);

    // 2) Per-head LayerNorm on q and k
    ln_kernel<<<(BB * HH * NN) / 8, 256>>>(0, q_gamma, q_beta);
    ln_kernel<<<(BB * HH * NN) / 8, 256>>>(1, k_gamma, k_beta);

    // 3) Attention -> g_att [B,N,C]
    attn_kernel<<<dim3(NN / 64, BB * HH), 256>>>(mask);

    // 4) Split attention output, project (tensor cores) + bias
    split_bf16<0><<<MM, 256>>>(attp, att2, MM * 256);
    gemm_mma<1><<<dim3(CC / 128, MM / 128), 256, GSMEM>>>(att2, wp2, b_proj, out);
}

// round 6
// speedup vs baseline: 1.8573x; 1.5076x over previous
#include <cuda_runtime.h>
#include <cuda_bf16.h>
#include <cstdint>
#include <cstddef>

// Problem constants
#define BB 2
#define NN 2048
#define CC 1024
#define HH 16
#define DD 64
#define MM (BB*NN)            // 4096
#define K3 3072               // 3-term split K for projection GEMMs

// Scratch (device globals; no allocation allowed)
__device__ float g_q[BB*HH*NN*DD];     // [B,H,N,d] fp32
__device__ float g_k[BB*HH*NN*DD];
__device__ float g_v[BB*HH*NN*DD];
__device__ float g_att[MM*CC];         // [B,N,C] attention output
__device__ __nv_bfloat16 g_x2[MM*K3];
__device__ __nv_bfloat16 g_wqkv2[3*CC*K3];
__device__ __nv_bfloat16 g_wp2[CC*K3];
__device__ __nv_bfloat16 g_att2[MM*K3];
// attention bf16 operands
__device__ __nv_bfloat16 g_qh[BB*HH*NN*DD];   // LN(q) hi
__device__ __nv_bfloat16 g_ql[BB*HH*NN*DD];   // LN(q) lo
__device__ __nv_bfloat16 g_kh[BB*HH*NN*DD];
__device__ __nv_bfloat16 g_kl[BB*HH*NN*DD];
__device__ __nv_bfloat16 g_vth[BB*HH*DD*NN];  // V^T hi: [bh][d][n]
__device__ __nv_bfloat16 g_vtl[BB*HH*DD*NN];  // V^T lo

// ---------------------------------------------------------------------------
// helpers
// ---------------------------------------------------------------------------
__device__ __forceinline__ uint32_t smem_u32(const void* p) {
    uint32_t a;
    asm("{ .reg .u64 t; cvta.to.shared.u64 t, %1; cvt.u32.u64 %0, t; }" : "=r"(a) : "l"(p));
    return a;
}
__device__ __forceinline__ void cp16(uint32_t dst, const void* src) {
    asm volatile("cp.async.cg.shared.global [%0], [%1], 16;" :: "r"(dst), "l"(src));
}
__device__ __forceinline__ void cp_commit() {
    asm volatile("cp.async.commit_group;" ::: "memory");
}
template<int N>
__device__ __forceinline__ void cp_wait() {
    asm volatile("cp.async.wait_group %0;" :: "n"(N) : "memory");
}
__device__ __forceinline__ void ldsm4(uint32_t addr, uint32_t& r0, uint32_t& r1,
                                      uint32_t& r2, uint32_t& r3) {
    asm volatile("ldmatrix.sync.aligned.m8n8.x4.shared.b16 {%0,%1,%2,%3}, [%4];"
                 : "=r"(r0), "=r"(r1), "=r"(r2), "=r"(r3) : "r"(addr));
}
__device__ __forceinline__ void mma_bf16(float* d, const uint32_t* a,
                                         uint32_t b0, uint32_t b1) {
    asm volatile(
        "mma.sync.aligned.m16n8k16.row.col.f32.bf16.bf16.f32 "
        "{%0,%1,%2,%3}, {%4,%5,%6,%7}, {%8,%9}, {%0,%1,%2,%3};"
        : "+f"(d[0]), "+f"(d[1]), "+f"(d[2]), "+f"(d[3])
        : "r"(a[0]), "r"(a[1]), "r"(a[2]), "r"(a[3]), "r"(b0), "r"(b1));
}
// pack(lo=a, hi=b)
__device__ __forceinline__ uint32_t packbf(float a, float b) {
    uint32_t r;
    asm("cvt.rn.bf16x2.f32 %0, %1, %2;" : "=r"(r) : "f"(b), "f"(a));
    return r;
}
__device__ __forceinline__ void split2(float v0, float v1, uint32_t& h, uint32_t& l) {
    h = packbf(v0, v1);
    float h0 = __uint_as_float(h << 16);
    float h1 = __uint_as_float(h & 0xFFFF0000u);
    l = packbf(v0 - h0, v1 - h1);
}
// fast exp2 for x <= 0 (clamped at -120); FMA-only, rel err ~2.4e-6
__device__ __forceinline__ float exp2p(float x) {
    x = fmaxf(x, -120.f);
    float t = x + 12582912.f;                    // round-to-int magic
    int   n = __float_as_int(t) - 0x4B400000;
    float f = x - (t - 12582912.f);              // f in [-0.5, 0.5]
    float p = 1.3333558146e-3f;
    p = fmaf(p, f, 9.6181291076e-3f);
    p = fmaf(p, f, 5.5504108664e-2f);
    p = fmaf(p, f, 2.4022650696e-1f);
    p = fmaf(p, f, 6.9314718056e-1f);
    p = fmaf(p, f, 1.0f);
    return __uint_as_float((uint32_t)(__float_as_int(p) + (n << 23)));
}

// ---------------------------------------------------------------------------
// Split fp32 row (1024) -> bf16 row (3072) for projection GEMMs.
// IS_B=0 (A operand): [hi | hi | lo].  IS_B=1 (B operand): [hi | lo | hi].
// ---------------------------------------------------------------------------
template<int IS_B>
__global__ void __launch_bounds__(256) split_bf16(const float* __restrict__ src,
                                                  __nv_bfloat16* __restrict__ dst, int n4)
{
    int i = blockIdx.x * 256 + threadIdx.x;
    if (i >= n4) return;
    int r = i >> 8, c4 = i & 255;
    float4 v = ((const float4*)src)[(size_t)r * 256 + c4];
    uint2 hv, lv;
    uint32_t h0, l0, h1, l1;
    split2(v.x, v.y, h0, l0);
    split2(v.z, v.w, h1, l1);
    hv.x = h0; hv.y = h1; lv.x = l0; lv.y = l1;
    uint2* base = (uint2*)(dst + (size_t)r * K3);
    base[c4]       = hv;
    base[256 + c4] = IS_B ? lv : hv;
    base[512 + c4] = IS_B ? hv : lv;
}

// ---------------------------------------------------------------------------
// bf16 mma.sync GEMM (unchanged from R5): C[m,n]=sum_k A2[m,k]*B2[n,k], K=3072.
// ---------------------------------------------------------------------------
#define GSTAGE 32768u
#define GSMEM  (3u * GSTAGE)

template<int MODE>
__global__ void __launch_bounds__(256, 2) gemm_mma(const __nv_bfloat16* __restrict__ A,
                                                   const __nv_bfloat16* __restrict__ Bm,
                                                   const float* __restrict__ bias,
                                                   float* __restrict__ Cout)
{
    extern __shared__ __align__(128) char smem[];
    const uint32_t sb = smem_u32(smem);
    const int tid  = threadIdx.x;
    const int wid  = tid >> 5;
    const int lane = tid & 31;
    const int wm = wid & 1;
    const int wn = wid >> 1;
    const int m0 = blockIdx.y * 128;
    const int n0 = blockIdx.x * 128;

    const int arow = tid >> 1;
    const int acb  = (tid & 1) * 4;
    const __nv_bfloat16* gA = A  + (size_t)(m0 + arow) * K3 + acb * 8;
    const __nv_bfloat16* gB = Bm + (size_t)(n0 + arow) * K3 + acb * 8;
    uint32_t sAo[4], sBo[4];
#pragma unroll
    for (int i = 0; i < 4; i++) {
        const int ch = acb + i;
        sAo[i] = (uint32_t)(arow * 128 + ((ch ^ (arow & 7)) * 16));
        sBo[i] = 16384u + sAo[i];
    }

    const int chAdd = lane >> 4;
    uint32_t aRow[4]; int aXor[4];
#pragma unroll
    for (int mt = 0; mt < 4; mt++) {
        const int r = wm * 64 + mt * 16 + ((lane >> 3) & 1) * 8 + (lane & 7);
        aRow[mt] = (uint32_t)(r * 128);
        aXor[mt] = r & 7;
    }
    uint32_t bRow[2]; int bXor[2];
#pragma unroll
    for (int ntp = 0; ntp < 2; ntp++) {
        const int r = wn * 32 + ntp * 16 + ((lane >> 3) & 1) * 8 + (lane & 7);
        bRow[ntp] = 16384u + (uint32_t)(r * 128);
        bXor[ntp] = r & 7;
    }

    float acc[4][4][4];
#pragma unroll
    for (int i = 0; i < 4; i++)
#pragma unroll
        for (int j = 0; j < 4; j++)
#pragma unroll
            for (int c = 0; c < 4; c++) acc[i][j][c] = 0.f;

#pragma unroll
    for (int st = 0; st < 2; st++) {
        const uint32_t base = sb + st * GSTAGE;
        const __nv_bfloat16* pa = gA + st * 64;
        const __nv_bfloat16* pb = gB + st * 64;
#pragma unroll
        for (int i = 0; i < 4; i++) { cp16(base + sAo[i], pa + i * 8); cp16(base + sBo[i], pb + i * 8); }
        cp_commit();
    }

    const int ITERS = K3 / 64;
    for (int it = 0; it < ITERS; it++) {
        if (it < ITERS - 1) cp_wait<1>(); else cp_wait<0>();
        __syncthreads();
        if (it + 2 < ITERS) {
            const uint32_t base = sb + ((it + 2) % 3) * GSTAGE;
            const __nv_bfloat16* pa = gA + (it + 2) * 64;
            const __nv_bfloat16* pb = gB + (it + 2) * 64;
#pragma unroll
            for (int i = 0; i < 4; i++) { cp16(base + sAo[i], pa + i * 8); cp16(base + sBo[i], pb + i * 8); }
            cp_commit();
        }
        const uint32_t base = sb + (it % 3) * GSTAGE;
#pragma unroll
        for (int kc = 0; kc < 4; kc++) {
            uint32_t a[4][4], b[2][4];
#pragma unroll
            for (int mt = 0; mt < 4; mt++)
                ldsm4(base + aRow[mt] + (uint32_t)(((kc * 2 + chAdd) ^ aXor[mt]) * 16),
                      a[mt][0], a[mt][1], a[mt][2], a[mt][3]);
#pragma unroll
            for (int ntp = 0; ntp < 2; ntp++)
                ldsm4(base + bRow[ntp] + (uint32_t)(((kc * 2 + chAdd) ^ bXor[ntp]) * 16),
                      b[ntp][0], b[ntp][1], b[ntp][2], b[ntp][3]);
#pragma unroll
            for (int mt = 0; mt < 4; mt++)
#pragma unroll
                for (int nt = 0; nt < 4; nt++)
                    mma_bf16(acc[mt][nt], a[mt],
                             b[nt >> 1][nt & 1], b[nt >> 1][(nt & 1) + 2]);
        }
        __syncthreads();
    }

#pragma unroll
    for (int mt = 0; mt < 4; mt++) {
#pragma unroll
        for (int nt = 0; nt < 4; nt++) {
            const int j  = n0 + wn * 32 + nt * 8 + (lane & 3) * 2;
            const int r0 = m0 + wm * 64 + mt * 16 + (lane >> 2);
#pragma unroll
            for (int half = 0; half < 2; half++) {
                const int m = r0 + half * 8;
                float2 v;
                v.x = acc[mt][nt][half * 2 + 0];
                v.y = acc[mt][nt][half * 2 + 1];
                if (MODE == 0) {
                    const int ssel = j >> 10;
                    const int h    = (j >> 6) & 15;
                    const int dd   = j & 63;
                    const int bi   = m >> 11;
                    const int n    = m & 2047;
                    float* dst = (ssel == 0) ? g_q : (ssel == 1) ? g_k : g_v;
                    *(float2*)&dst[(((size_t)(bi * HH + h) * NN + n) << 6) + dd] = v;
                } else {
                    float2 bv = *(const float2*)&bias[j];
                    v.x += bv.x; v.y += bv.y;
                    *(float2*)&Cout[(size_t)m * CC + j] = v;
                }
            }
        }
    }
}

// ---------------------------------------------------------------------------
// LayerNorm (d=64) fused with bf16 hi/lo split. One warp per (bh,n) row.
// which==0: g_q -> g_qh/g_ql.  which==1: g_k -> g_kh/g_kl.
// ---------------------------------------------------------------------------
__global__ void __launch_bounds__(256) qkln_split(int which,
                                                  const float* __restrict__ gamma,
                                                  const float* __restrict__ beta)
{
    const float* src = which ? g_k : g_q;
    __nv_bfloat16* dh = which ? g_kh : g_qh;
    __nv_bfloat16* dl = which ? g_kl : g_ql;
    const int row  = blockIdx.x * 8 + (threadIdx.x >> 5);
    const int lane = threadIdx.x & 31;
    float2 v = *(float2*)&src[(size_t)row * 64 + lane * 2];
    float s  = v.x + v.y;
    float sq = v.x * v.x + v.y * v.y;
#pragma unroll
    for (int m = 16; m >= 1; m >>= 1) {
        s  += __shfl_xor_sync(0xffffffffu, s,  m);
        sq += __shfl_xor_sync(0xffffffffu, sq, m);
    }
    const float mean = s * (1.f / 64.f);
    const float var  = sq * (1.f / 64.f) - mean * mean;
    const float rstd = rsqrtf(var + 1e-5f);
    float2 g  = *(const float2*)&gamma[lane * 2];
    float2 be = *(const float2*)&beta[lane * 2];
    float y0 = (v.x - mean) * rstd * g.x + be.x;
    float y1 = (v.y - mean) * rstd * g.y + be.y;
    uint32_t h, l;
    split2(y0, y1, h, l);
    *(uint32_t*)&dh[(size_t)row * 64 + lane * 2] = h;
    *(uint32_t*)&dl[(size_t)row * 64 + lane * 2] = l;
}

// ---------------------------------------------------------------------------
// V -> V^T with bf16 hi/lo split. CTA per (jt, bh): 64x64 tile.
// g_vth[bh][d][n], g_vtl likewise.
// ---------------------------------------------------------------------------
__global__ void __launch_bounds__(256) vt_split()
{
    __shared__ float vs[64][65];
    const int jt = blockIdx.x, bh = blockIdx.y;
    const float* V = g_v + ((size_t)bh * NN + jt * 64) * 64;
#pragma unroll
    for (int k = 0; k < 4; k++) {
        const int i = threadIdx.x + k * 256;
        const int r = i >> 4, c4 = i & 15;
        float4 t = *(const float4*)&V[(size_t)r * 64 + c4 * 4];
        vs[r][c4 * 4 + 0] = t.x; vs[r][c4 * 4 + 1] = t.y;
        vs[r][c4 * 4 + 2] = t.z; vs[r][c4 * 4 + 3] = t.w;
    }
    __syncthreads();
    const int d = threadIdx.x >> 2, jg = threadIdx.x & 3;
    uint32_t hp[8], lp[8];
#pragma unroll
    for (int i = 0; i < 8; i++) {
        float v0 = vs[jg * 16 + 2 * i + 0][d];
        float v1 = vs[jg * 16 + 2 * i + 1][d];
        split2(v0, v1, hp[i], lp[i]);
    }
    const size_t off = (size_t)bh * (DD * NN) + (size_t)d * NN + jt * 64 + jg * 16;
    uint4* oh = (uint4*)(g_vth + off);
    uint4* ol = (uint4*)(g_vtl + off);
    oh[0] = make_uint4(hp[0], hp[1], hp[2], hp[3]);
    oh[1] = make_uint4(hp[4], hp[5], hp[6], hp[7]);
    ol[0] = make_uint4(lp[0], lp[1], lp[2], lp[3]);
    ol[1] = make_uint4(lp[4], lp[5], lp[6], lp[7]);
}

// ---------------------------------------------------------------------------
// Tensor-core flash attention. CTA: 128 queries x one (b,h); 8 warps, 16 q/warp.
// Key tiles of 64, double-buffered smem {Kh,Kl,Vh,Vl} 8KB each (32KB/stage).
// S via (qh,kh)+(qh,kl)+(ql,kh); PV via (ph,vh)+(ph,vl)+(pl,vh).
// Softmax in base-2 with FMA-only exp2.
// ---------------------------------------------------------------------------
#define ASTAGE 32768u
#define ASMEM  (2u * ASTAGE)

__global__ void __launch_bounds__(256) attn_tc(const unsigned char* __restrict__ mask)
{
    extern __shared__ __align__(128) char smem[];
    const uint32_t sb = smem_u32(smem);
    const int tid  = threadIdx.x;
    const int wid  = tid >> 5;
    const int lane = tid & 31;
    const int bh = blockIdx.y;
    const int b  = bh >> 4;
    const int h  = bh & 15;
    const int q0 = blockIdx.x * 128;

    const __nv_bfloat16* Qh = g_qh + (size_t)bh * (NN * DD);
    const __nv_bfloat16* Ql = g_ql + (size_t)bh * (NN * DD);
    const __nv_bfloat16* Kh = g_kh + (size_t)bh * (NN * DD);
    const __nv_bfloat16* Kl = g_kl + (size_t)bh * (NN * DD);
    const __nv_bfloat16* Vh = g_vth + (size_t)bh * (DD * NN);
    const __nv_bfloat16* Vl = g_vtl + (size_t)bh * (DD * NN);

    // ---- stage Q (qh at 0, ql at 16384) and build A-frags ----
    {
        const int r  = tid >> 1;
        const int cb = (tid & 1) * 4;
        const __nv_bfloat16* gq  = Qh + (size_t)(q0 + r) * 64 + cb * 8;
        const __nv_bfloat16* gq2 = Ql + (size_t)(q0 + r) * 64 + cb * 8;
#pragma unroll
        for (int i = 0; i < 4; i++) {
            const int ch = cb + i;
            const uint32_t so = (uint32_t)(r * 128 + ((ch ^ (r & 7)) * 16));
            cp16(sb + so, gq + i * 8);
            cp16(sb + 16384u + so, gq2 + i * 8);
        }
        cp_commit(); cp_wait<0>(); __syncthreads();
    }
    uint32_t qh[4][4], ql[4][4];
    {
        const int r  = wid * 16 + ((lane >> 3) & 1) * 8 + (lane & 7);
        const int rx = r & 7;
        const int ca = lane >> 4;
#pragma unroll
        for (int kc = 0; kc < 4; kc++) {
            const uint32_t co = (uint32_t)(((kc * 2 + ca) ^ rx) * 16);
            ldsm4(sb + (uint32_t)(r * 128) + co, qh[kc][0], qh[kc][1], qh[kc][2], qh[kc][3]);
            ldsm4(sb + 16384u + (uint32_t)(r * 128) + co, ql[kc][0], ql[kc][1], ql[kc][2], ql[kc][3]);
        }
    }
    __syncthreads();

    // ---- K/V tile loader geometry ----
    const int sub = tid >> 6;          // 0:Kh 1:Kl 2:Vh 3:Vl
    const int lr  = tid & 63;
    const int lrx = lr & 7;
    const __nv_bfloat16* lbase =
        (sub == 0) ? (Kh + (size_t)lr * 64) :
        (sub == 1) ? (Kl + (size_t)lr * 64) :
        (sub == 2) ? (Vh + (size_t)lr * NN) : (Vl + (size_t)lr * NN);
    const int lstep = (sub < 2) ? (64 * 64) : 64;
    const uint32_t sdst = sb + (uint32_t)(sub * 8192 + lr * 128);

#define LOAD_TILE(jt, buf) do { \
    const __nv_bfloat16* _s = lbase + (size_t)(jt) * lstep; \
    const uint32_t _d = sdst + (buf) * ASTAGE; \
    _Pragma("unroll") \
    for (int c = 0; c < 8; c++) cp16(_d + (uint32_t)(((c ^ lrx) * 16)), _s + c * 8); \
} while (0)

    LOAD_TILE(0, 0); cp_commit();

    // softmax state (2 rows per thread: lr0 = lane>>2, lr1 = lr0+8 within warp's 16)
    float m0 = -1e30f, m1 = -1e30f, l0 = 0.f, l1 = 0.f;
    float o[8][4];
#pragma unroll
    for (int nt = 0; nt < 8; nt++)
#pragma unroll
        for (int c = 0; c < 4; c++) o[nt][c] = 0.f;

    const unsigned char* mr0 =
        mask + (size_t)(b * NN + q0 + wid * 16 + (lane >> 2)) * NN;
    const unsigned char* mr1 = mr0 + (size_t)8 * NN;

    const int br = ((lane >> 3) & 1) * 8 + (lane & 7);
    const int ca = lane >> 4;
    const float SC2 = 0.125f * 1.44269504088896341f;

    for (int jt = 0; jt < NN / 64; jt++) {
        cp_wait<0>(); __syncthreads();
        if (jt + 1 < NN / 64) { LOAD_TILE(jt + 1, (jt + 1) & 1); cp_commit(); }
        const uint32_t kb = sb + (uint32_t)(jt & 1) * ASTAGE;

        // ---- S = Q K^T, 3 passes ----
        float s[8][4];
#pragma unroll
        for (int nt = 0; nt < 8; nt++)
#pragma unroll
            for (int c = 0; c < 4; c++) s[nt][c] = 0.f;
#pragma unroll
        for (int pass = 0; pass < 3; pass++) {
            const uint32_t bbase = kb + (pass == 1 ? 8192u : 0u);
            const uint32_t (*af)[4] = (pass == 2) ? ql : qh;
#pragma unroll
            for (int kc = 0; kc < 4; kc++) {
                uint32_t bf[4][4];
#pragma unroll
                for (int ntp = 0; ntp < 4; ntp++) {
                    const int rr = ntp * 16 + br;
                    ldsm4(bbase + (uint32_t)(rr * 128 + (((kc * 2 + ca) ^ (rr & 7)) * 16)),
                          bf[ntp][0], bf[ntp][1], bf[ntp][2], bf[ntp][3]);
                }
#pragma unroll
                for (int nt = 0; nt < 8; nt++)
                    mma_bf16(s[nt], af[kc], bf[nt >> 1][nt & 1], bf[nt >> 1][(nt & 1) + 2]);
            }
        }

        // ---- scale (base-2) + mask ----
        const int j0 = jt * 64;
#pragma unroll
        for (int nt = 0; nt < 8; nt++) {
            const int jc = j0 + nt * 8 + (lane & 3) * 2;
            uchar2 mv0 = *(const uchar2*)&mr0[jc];
            uchar2 mv1 = *(const uchar2*)&mr1[jc];
            s[nt][0] = mv0.x ? -1e30f : s[nt][0] * SC2;
            s[nt][1] = mv0.y ? -1e30f : s[nt][1] * SC2;
            s[nt][2] = mv1.x ? -1e30f : s[nt][2] * SC2;
            s[nt][3] = mv1.y ? -1e30f : s[nt][3] * SC2;
        }

        // ---- online softmax ----
        float mx0 = -1e30f, mx1 = -1e30f;
#pragma unroll
        for (int nt = 0; nt < 8; nt++) {
            mx0 = fmaxf(mx0, fmaxf(s[nt][0], s[nt][1]));
            mx1 = fmaxf(mx1, fmaxf(s[nt][2], s[nt][3]));
        }
        mx0 = fmaxf(mx0, __shfl_xor_sync(0xffffffffu, mx0, 1));
        mx0 = fmaxf(mx0, __shfl_xor_sync(0xffffffffu, mx0, 2));
        mx1 = fmaxf(mx1, __shfl_xor_sync(0xffffffffu, mx1, 1));
        mx1 = fmaxf(mx1, __shfl_xor_sync(0xffffffffu, mx1, 2));
        const float mn0 = fmaxf(m0, mx0);
        const float mn1 = fmaxf(m1, mx1);
        const float a0 = exp2p(m0 - mn0);
        const float a1 = exp2p(m1 - mn1);
        m0 = mn0; m1 = mn1;
        float ls0 = 0.f, ls1 = 0.f;
#pragma unroll
        for (int nt = 0; nt < 8; nt++) {
            s[nt][0] = exp2p(s[nt][0] - mn0); ls0 += s[nt][0];
            s[nt][1] = exp2p(s[nt][1] - mn0); ls0 += s[nt][1];
            s[nt][2] = exp2p(s[nt][2] - mn1); ls1 += s[nt][2];
            s[nt][3] = exp2p(s[nt][3] - mn1); ls1 += s[nt][3];
        }
        ls0 += __shfl_xor_sync(0xffffffffu, ls0, 1);
        ls0 += __shfl_xor_sync(0xffffffffu, ls0, 2);
        ls1 += __shfl_xor_sync(0xffffffffu, ls1, 1);
        ls1 += __shfl_xor_sync(0xffffffffu, ls1, 2);
        l0 = l0 * a0 + ls0;
        l1 = l1 * a1 + ls1;
#pragma unroll
        for (int nt = 0; nt < 8; nt++) {
            o[nt][0] *= a0; o[nt][1] *= a0;
            o[nt][2] *= a1; o[nt][3] *= a1;
        }

        // ---- split P into hi/lo A-frags ----
        uint32_t aph[4][4], apl[4][4];
#pragma unroll
        for (int kc = 0; kc < 4; kc++) {
            split2(s[2*kc][0],   s[2*kc][1],   aph[kc][0], apl[kc][0]);
            split2(s[2*kc][2],   s[2*kc][3],   aph[kc][1], apl[kc][1]);
            split2(s[2*kc+1][0], s[2*kc+1][1], aph[kc][2], apl[kc][2]);
            split2(s[2*kc+1][2], s[2*kc+1][3], aph[kc][3], apl[kc][3]);
        }

        // ---- O += P V, 3 passes ----
#pragma unroll
        for (int pass = 0; pass < 3; pass++) {
            const uint32_t vb = kb + 16384u + (pass == 1 ? 8192u : 0u);
            const uint32_t (*af)[4] = (pass == 2) ? apl : aph;
#pragma unroll
            for (int kc = 0; kc < 4; kc++) {
                uint32_t bf[4][4];
#pragma unroll
                for (int ntp = 0; ntp < 4; ntp++) {
                    const int rr = ntp * 16 + br;
                    ldsm4(vb + (uint32_t)(rr * 128 + (((kc * 2 + ca) ^ (rr & 7)) * 16)),
                          bf[ntp][0], bf[ntp][1], bf[ntp][2], bf[ntp][3]);
                }
#pragma unroll
                for (int nt = 0; nt < 8; nt++)
                    mma_bf16(o[nt], af[kc], bf[nt >> 1][nt & 1], bf[nt >> 1][(nt & 1) + 2]);
            }
        }
    }

    // ---- epilogue ----
    const float inv0 = 1.f / l0;
    const float inv1 = 1.f / l1;
    const int row0 = q0 + wid * 16 + (lane >> 2);
#pragma unroll
    for (int nt = 0; nt < 8; nt++) {
        const int col = h * 64 + nt * 8 + (lane & 3) * 2;
        float2 v0 = make_float2(o[nt][0] * inv0, o[nt][1] * inv0);
        float2 v1 = make_float2(o[nt][2] * inv1, o[nt][3] * inv1);
        *(float2*)&g_att[(size_t)(b * NN + row0) * CC + col]     = v0;
        *(float2*)&g_att[(size_t)(b * NN + row0 + 8) * CC + col] = v1;
    }
#undef LOAD_TILE
}

// ---------------------------------------------------------------------------
extern "C" void kernel_launch(void* const* d_in, const int* in_sizes, int n_in,
                              void* d_out, int out_size)
{
    const float*         x       = (const float*)d_in[0];
    const unsigned char* mask    = (const unsigned char*)d_in[1];
    const float*         w_qkv   = (const float*)d_in[2];
    const float*         w_proj  = (const float*)d_in[3];
    const float*         b_proj  = (const float*)d_in[4];
    const float*         q_gamma = (const float*)d_in[5];
    const float*         q_beta  = (const float*)d_in[6];
    const float*         k_gamma = (const float*)d_in[7];
    const float*         k_beta  = (const float*)d_in[8];
    float*               out     = (float*)d_out;

    __nv_bfloat16 *x2, *wq2, *wp2, *att2;
    float *attp;
    cudaGetSymbolAddress((void**)&x2,   g_x2);
    cudaGetSymbolAddress((void**)&wq2,  g_wqkv2);
    cudaGetSymbolAddress((void**)&wp2,  g_wp2);
    cudaGetSymbolAddress((void**)&att2, g_att2);
    cudaGetSymbolAddress((void**)&attp, g_att);

    cudaFuncSetAttribute(gemm_mma<0>, cudaFuncAttributeMaxDynamicSharedMemorySize, GSMEM);
    cudaFuncSetAttribute(gemm_mma<1>, cudaFuncAttributeMaxDynamicSharedMemorySize, GSMEM);
    cudaFuncSetAttribute(attn_tc, cudaFuncAttributeMaxDynamicSharedMemorySize, ASMEM);

    // 0) bf16 3-term splits for projection GEMMs
    split_bf16<0><<<MM, 256>>>(x, x2, MM * 256);
    split_bf16<1><<<3 * CC, 256>>>(w_qkv, wq2, 3 * CC * 256);
    split_bf16<1><<<CC, 256>>>(w_proj, wp2, CC * 256);

    // 1) QKV projection -> q/k/v fp32
    gemm_mma<0><<<dim3(3 * CC / 128, MM / 128), 256, GSMEM>>>(x2, wq2, nullptr, nullptr);

    // 2) LN + split q,k; transpose + split v
    qkln_split<<<(BB * HH * NN) / 8, 256>>>(0, q_gamma, q_beta);
    qkln_split<<<(BB * HH * NN) / 8, 256>>>(1, k_gamma, k_beta);
    vt_split<<<dim3(NN / 64, BB * HH), 256>>>();

    // 3) Tensor-core flash attention -> g_att
    attn_tc<<<dim3(NN / 128, BB * HH), 256, ASMEM>>>(mask);

    // 4) Output projection + bias
    split_bf16<0><<<MM, 256>>>(attp, att2, MM * 256);
    gemm_mma<1><<<dim3(CC / 128, MM / 128), 256, GSMEM>>>(att2, wp2, b_proj, out);
}